// round 3
// baseline (speedup 1.0000x reference)
#include <cuda_runtime.h>
#include <math.h>

// Problem dims (fixed)
#define BB 4
#define SS 2048
#define EE 512
#define HH 8
#define DD 64
#define FF 2048
#define MM (BB*SS)          // 8192 tokens
#define LN_EPS 1e-5f

// ---------------- scratch (device globals; no allocation) ----------------
__device__ float g_Q  [MM*EE];
__device__ float g_K  [MM*EE];
__device__ float g_V  [MM*EE];
__device__ float g_ctx[MM*EE];
__device__ float g_tmp[MM*EE];
__device__ float g_x1 [MM*EE];
__device__ float g_ffn[MM*FF];

// ---------------- generic tiled fp32 GEMM: C = A[M,K] @ B[K,N] + epi ----------------
// EPI: 0 = +bias ; 1 = +bias + residual ; 2 = gelu(+bias)
template<int EPI>
__global__ __launch_bounds__(256) void gemm_kernel(
    const float* __restrict__ A, const float* __restrict__ Bm,
    const float* __restrict__ bias, const float* __restrict__ res,
    float* __restrict__ C, int M, int N, int K)
{
    constexpr int BM = 128, BN = 128, BK = 16;
    __shared__ float As[BK][BM];   // A tile transposed
    __shared__ float Bs[BK][BN];

    const int tid = threadIdx.x;
    const int ty = tid >> 4;       // 0..15
    const int tx = tid & 15;       // 0..15
    const int m0 = blockIdx.y * BM;
    const int n0 = blockIdx.x * BN;

    float acc[8][8];
    #pragma unroll
    for (int i = 0; i < 8; i++)
        #pragma unroll
        for (int j = 0; j < 8; j++) acc[i][j] = 0.f;

    for (int k0 = 0; k0 < K; k0 += BK) {
        // load A tile: 128 rows x 16 cols = 512 float4
        #pragma unroll
        for (int i = 0; i < 2; i++) {
            int lin = tid + i * 256;
            int row = lin >> 2;
            int c4  = (lin & 3) * 4;
            float4 v = *(const float4*)(A + (size_t)(m0 + row) * K + k0 + c4);
            As[c4+0][row] = v.x; As[c4+1][row] = v.y;
            As[c4+2][row] = v.z; As[c4+3][row] = v.w;
        }
        // load B tile: 16 rows x 128 cols = 512 float4
        #pragma unroll
        for (int i = 0; i < 2; i++) {
            int lin = tid + i * 256;
            int row = lin >> 5;
            int c4  = (lin & 31) * 4;
            *(float4*)(&Bs[row][c4]) =
                *(const float4*)(Bm + (size_t)(k0 + row) * N + n0 + c4);
        }
        __syncthreads();

        #pragma unroll
        for (int kk = 0; kk < BK; kk++) {
            float a[8], b[8];
            #pragma unroll
            for (int j = 0; j < 8; j++) a[j] = As[kk][ty*8 + j];
            #pragma unroll
            for (int j = 0; j < 8; j++) b[j] = Bs[kk][tx*8 + j];
            #pragma unroll
            for (int i = 0; i < 8; i++)
                #pragma unroll
                for (int j = 0; j < 8; j++)
                    acc[i][j] += a[i] * b[j];
        }
        __syncthreads();
    }

    // epilogue
    #pragma unroll
    for (int i = 0; i < 8; i++) {
        int row = m0 + ty*8 + i;
        #pragma unroll
        for (int j = 0; j < 8; j++) {
            int col = n0 + tx*8 + j;
            float v = acc[i][j] + bias[col];
            if (EPI == 1) v += res[(size_t)row * N + col];
            if (EPI == 2) v = 0.5f * v * (1.0f + erff(v * 0.70710678118654752f));
            C[(size_t)row * N + col] = v;
        }
    }
}

// ---------------- flash attention (fp32, online softmax) ----------------
// grid: (S/64, H, B), block 256. Each block: 64 q-rows for one (b,h).
// Thread micro-tile: 4 q-rows (tr*4..) x 4 cols (tc*4..) for scores and O.
__global__ __launch_bounds__(256) void attn_kernel(
    const float* __restrict__ Q, const float* __restrict__ K,
    const float* __restrict__ V, float* __restrict__ O)
{
    extern __shared__ float sm[];
    float* Qs = sm;               // [64][64], stride 64 (Q pre-scaled by 1/8)
    float* Kt = sm + 4096;        // [64 d][68] K transposed; reused as P [64 q][68]
    float* Vs = sm + 4096 + 4352; // [64 k][68]

    const int tid = threadIdx.x;
    const int tr = tid >> 4;      // q-row group 0..15
    const int tc = tid & 15;      // col group 0..15
    const int b = blockIdx.z, h = blockIdx.y;
    const int q0 = blockIdx.x * 64;
    const float scale = 0.125f;   // 1/sqrt(64)

    const size_t baseQ = ((size_t)(b * SS + q0)) * EE + h * DD;

    // load Q tile (scaled)
    #pragma unroll
    for (int i = 0; i < 4; i++) {
        int lin = tid + i * 256;          // 1024 float4
        int row = lin >> 4;
        int c4  = (lin & 15) * 4;
        float4 v = *(const float4*)(Q + baseQ + (size_t)row * EE + c4);
        v.x *= scale; v.y *= scale; v.z *= scale; v.w *= scale;
        *(float4*)(Qs + row * 64 + c4) = v;
    }

    float m_run[4], l_run[4], acc[4][4];
    #pragma unroll
    for (int i = 0; i < 4; i++) {
        m_run[i] = -1e30f; l_run[i] = 0.f;
        #pragma unroll
        for (int j = 0; j < 4; j++) acc[i][j] = 0.f;
    }

    for (int kt = 0; kt < SS / 64; kt++) {
        const size_t baseK = ((size_t)(b * SS + kt * 64)) * EE + h * DD;
        __syncthreads();  // prior P/V reads done (also covers Qs on first iter)

        // load K (transposed into Kt) and V
        #pragma unroll
        for (int i = 0; i < 4; i++) {
            int lin = tid + i * 256;
            int row = lin >> 4;           // key index
            int c4  = (lin & 15) * 4;     // d0
            float4 kv = *(const float4*)(K + baseK + (size_t)row * EE + c4);
            Kt[(c4+0)*68 + row] = kv.x;
            Kt[(c4+1)*68 + row] = kv.y;
            Kt[(c4+2)*68 + row] = kv.z;
            Kt[(c4+3)*68 + row] = kv.w;
            float4 vv = *(const float4*)(V + baseK + (size_t)row * EE + c4);
            *(float4*)(Vs + row * 68 + c4) = vv;
        }
        __syncthreads();

        // scores: s[ii][jj] = sum_d Qs[r][d] * K[k][d]
        float s[4][4];
        #pragma unroll
        for (int i = 0; i < 4; i++)
            #pragma unroll
            for (int j = 0; j < 4; j++) s[i][j] = 0.f;

        #pragma unroll 16
        for (int d = 0; d < 64; d++) {
            float4 k4 = *(const float4*)(Kt + d * 68 + tc * 4);
            #pragma unroll
            for (int ii = 0; ii < 4; ii++) {
                float q = Qs[(tr*4 + ii) * 64 + d];
                s[ii][0] += q * k4.x;
                s[ii][1] += q * k4.y;
                s[ii][2] += q * k4.z;
                s[ii][3] += q * k4.w;
            }
        }

        // online softmax update (per q-row; 16 tc-lanes share a row)
        #pragma unroll
        for (int ii = 0; ii < 4; ii++) {
            float mloc = fmaxf(fmaxf(s[ii][0], s[ii][1]), fmaxf(s[ii][2], s[ii][3]));
            #pragma unroll
            for (int off = 1; off < 16; off <<= 1)
                mloc = fmaxf(mloc, __shfl_xor_sync(0xffffffffu, mloc, off));
            float m_new = fmaxf(m_run[ii], mloc);
            float corr = __expf(m_run[ii] - m_new);
            m_run[ii] = m_new;
            #pragma unroll
            for (int jj = 0; jj < 4; jj++) s[ii][jj] = __expf(s[ii][jj] - m_new);
            float ls = s[ii][0] + s[ii][1] + s[ii][2] + s[ii][3];
            #pragma unroll
            for (int off = 1; off < 16; off <<= 1)
                ls += __shfl_xor_sync(0xffffffffu, ls, off);
            l_run[ii] = l_run[ii] * corr + ls;
            #pragma unroll
            for (int jj = 0; jj < 4; jj++) acc[ii][jj] *= corr;
        }

        __syncthreads();  // Kt score-reads done before P overwrite (alias)
        #pragma unroll
        for (int ii = 0; ii < 4; ii++)
            *(float4*)(Kt + (tr*4 + ii) * 68 + tc * 4) =
                make_float4(s[ii][0], s[ii][1], s[ii][2], s[ii][3]);
        __syncthreads();

        // O += P @ V  (thread dims dd = tc*4 + jj)
        #pragma unroll 16
        for (int k = 0; k < 64; k++) {
            float4 v4 = *(const float4*)(Vs + k * 68 + tc * 4);
            #pragma unroll
            for (int ii = 0; ii < 4; ii++) {
                float p = Kt[(tr*4 + ii) * 68 + k];
                acc[ii][0] += p * v4.x;
                acc[ii][1] += p * v4.y;
                acc[ii][2] += p * v4.z;
                acc[ii][3] += p * v4.w;
            }
        }
    }

    // write ctx (head h occupies cols h*64..h*64+63 -> concat layout)
    const size_t baseO = ((size_t)(b * SS + q0)) * EE + h * DD;
    #pragma unroll
    for (int ii = 0; ii < 4; ii++) {
        float inv = 1.0f / l_run[ii];
        float4 o = make_float4(acc[ii][0]*inv, acc[ii][1]*inv,
                               acc[ii][2]*inv, acc[ii][3]*inv);
        *(float4*)(O + baseO + (size_t)(tr*4 + ii) * EE + tc * 4) = o;
    }
}

// ---------------- layernorm: one block per row of 512 ----------------
__global__ __launch_bounds__(256) void ln_kernel(
    const float* __restrict__ x, const float* __restrict__ g,
    const float* __restrict__ be, float* __restrict__ y)
{
    __shared__ float red[16];
    const int row = blockIdx.x;
    const int tid = threadIdx.x;
    const float* xr = x + (size_t)row * EE;

    float v0 = xr[tid], v1 = xr[tid + 256];
    float s  = v0 + v1;
    float ss = v0*v0 + v1*v1;
    #pragma unroll
    for (int off = 16; off > 0; off >>= 1) {
        s  += __shfl_xor_sync(0xffffffffu, s,  off);
        ss += __shfl_xor_sync(0xffffffffu, ss, off);
    }
    int wid = tid >> 5, lid = tid & 31;
    if (lid == 0) { red[wid] = s; red[wid + 8] = ss; }
    __syncthreads();
    if (tid < 32) {
        float a = (tid < 8)  ? red[tid]     : 0.f;
        float c = (tid < 8)  ? red[tid + 8] : 0.f;
        #pragma unroll
        for (int off = 4; off > 0; off >>= 1) {
            a += __shfl_xor_sync(0xffffffffu, a, off);
            c += __shfl_xor_sync(0xffffffffu, c, off);
        }
        if (tid == 0) { red[0] = a; red[1] = c; }
    }
    __syncthreads();
    float mean = red[0] * (1.0f / EE);
    float var  = fmaxf(red[1] * (1.0f / EE) - mean * mean, 0.f);
    float rstd = rsqrtf(var + LN_EPS);

    float* yr = y + (size_t)row * EE;
    yr[tid]       = (v0 - mean) * rstd * g[tid]       + be[tid];
    yr[tid + 256] = (v1 - mean) * rstd * g[tid + 256] + be[tid + 256];
}

// ---------------- launch ----------------
extern "C" void kernel_launch(void* const* d_in, const int* in_sizes, int n_in,
                              void* d_out, int out_size)
{
    (void)in_sizes; (void)n_in; (void)out_size;
    const float* query = (const float*)d_in[0];
    const float* key_t = (const float*)d_in[1];
    const float* value = (const float*)d_in[2];
    const float* Wq = (const float*)d_in[3];  const float* bq = (const float*)d_in[4];
    const float* Wk = (const float*)d_in[5];  const float* bk = (const float*)d_in[6];
    const float* Wv = (const float*)d_in[7];  const float* bv = (const float*)d_in[8];
    const float* Wo = (const float*)d_in[9];  const float* bo = (const float*)d_in[10];
    const float* g1 = (const float*)d_in[11]; const float* be1 = (const float*)d_in[12];
    const float* g2 = (const float*)d_in[13]; const float* be2 = (const float*)d_in[14];
    const float* W1 = (const float*)d_in[15]; const float* b1 = (const float*)d_in[16];
    const float* W2 = (const float*)d_in[17]; const float* b2 = (const float*)d_in[18];
    float* out = (float*)d_out;

    void *pQ, *pK, *pV, *pCtx, *pTmp, *pX1, *pFfn;
    cudaGetSymbolAddress(&pQ,   g_Q);
    cudaGetSymbolAddress(&pK,   g_K);
    cudaGetSymbolAddress(&pV,   g_V);
    cudaGetSymbolAddress(&pCtx, g_ctx);
    cudaGetSymbolAddress(&pTmp, g_tmp);
    cudaGetSymbolAddress(&pX1,  g_x1);
    cudaGetSymbolAddress(&pFfn, g_ffn);
    float* fQ = (float*)pQ;   float* fK = (float*)pK;  float* fV = (float*)pV;
    float* fC = (float*)pCtx; float* fT = (float*)pTmp; float* fX = (float*)pX1;
    float* fF = (float*)pFfn;

    const int ATTN_SMEM = (4096 + 4352 + 4352) * 4;  // 51200 bytes
    cudaFuncSetAttribute(attn_kernel,
                         cudaFuncAttributeMaxDynamicSharedMemorySize, ATTN_SMEM);

    dim3 gProj(EE / 128, MM / 128);    // (4, 64)
    dim3 gFfn1(FF / 128, MM / 128);    // (16, 64)

    // 1-3: QKV projections
    gemm_kernel<0><<<gProj, 256>>>(query, Wq, bq, nullptr, fQ, MM, EE, EE);
    gemm_kernel<0><<<gProj, 256>>>(key_t, Wk, bk, nullptr, fK, MM, EE, EE);
    gemm_kernel<0><<<gProj, 256>>>(value, Wv, bv, nullptr, fV, MM, EE, EE);

    // 4: fused flash attention -> ctx (concat-head layout)
    attn_kernel<<<dim3(SS / 64, HH, BB), 256, ATTN_SMEM>>>(fQ, fK, fV, fC);

    // 5: O projection + residual(query)
    gemm_kernel<1><<<gProj, 256>>>(fC, Wo, bo, query, fT, MM, EE, EE);
    // 6: LN1
    ln_kernel<<<MM, 256>>>(fT, g1, be1, fX);
    // 7: FFN1 + exact GELU
    gemm_kernel<2><<<gFfn1, 256>>>(fX, W1, b1, nullptr, fF, MM, FF, EE);
    // 8: FFN2 + residual(x1)
    gemm_kernel<1><<<gProj, 256>>>(fF, W2, b2, fX, fT, MM, EE, FF);
    // 9: LN2 -> out
    ln_kernel<<<MM, 256>>>(fT, g2, be2, out);
}

// round 6
// speedup vs baseline: 1.3558x; 1.3558x over previous
#include <cuda_runtime.h>
#include <cuda_bf16.h>
#include <math.h>
#include <stdint.h>

// Problem dims (fixed)
#define BB 4
#define SS 2048
#define EE 512
#define HH 8
#define DD 64
#define FF 2048
#define MM (BB*SS)          // 8192 tokens
#define LN_EPS 1e-5f
#define K3E (3*EE)          // 1536  (split-K for K=512)
#define K3F (3*FF)          // 6144  (split-K for K=2048)

// ---------------- scratch (device globals; no allocation) ----------------
__device__ float g_Q  [MM*EE];
__device__ float g_K  [MM*EE];
__device__ float g_V  [MM*EE];
__device__ float g_tmp[MM*EE];
__device__ float g_x1 [MM*EE];
__device__ __nv_bfloat16 g_actA[(size_t)MM*K3E];   // split activations (K=512 stages)
__device__ __nv_bfloat16 g_actB[(size_t)MM*K3F];   // split FFN1 output (K=2048 stage)
__device__ __nv_bfloat16 g_ws  [(size_t)FF*K3E];   // split weights (max 2048*1536 == 512*6144)

// ================= helpers =================
__device__ __forceinline__ uint32_t smem_u32(const void* p) {
    uint32_t a;
    asm("{ .reg .u64 t; cvta.to.shared.u64 t, %1; cvt.u32.u64 %0, t; }"
        : "=r"(a) : "l"(p));
    return a;
}
__device__ __forceinline__ void cpasync16(uint32_t s, const void* g) {
    asm volatile("cp.async.cg.shared.global [%0], [%1], 16;" :: "r"(s), "l"(g));
}
__device__ __forceinline__ void cp_commit() {
    asm volatile("cp.async.commit_group;" ::: "memory");
}
__device__ __forceinline__ void ldm_x4(uint32_t* r, uint32_t addr) {
    asm volatile("ldmatrix.sync.aligned.m8n8.x4.shared.b16 {%0,%1,%2,%3}, [%4];"
        : "=r"(r[0]), "=r"(r[1]), "=r"(r[2]), "=r"(r[3]) : "r"(addr));
}
__device__ __forceinline__ void mma_bf16(float* c, const uint32_t* a,
                                         uint32_t b0, uint32_t b1) {
    asm volatile(
        "mma.sync.aligned.m16n8k16.row.col.f32.bf16.bf16.f32 "
        "{%0,%1,%2,%3}, {%4,%5,%6,%7}, {%8,%9}, {%0,%1,%2,%3};"
        : "+f"(c[0]), "+f"(c[1]), "+f"(c[2]), "+f"(c[3])
        : "r"(a[0]), "r"(a[1]), "r"(a[2]), "r"(a[3]), "r"(b0), "r"(b1));
}
__device__ __forceinline__ uint32_t pk2(__nv_bfloat16 a, __nv_bfloat16 b) {
    __nv_bfloat162 t = __halves2bfloat162(a, b);
    return *reinterpret_cast<uint32_t*>(&t);
}

// ================= HMMA (mma.sync) GEMM =================
// C[M,N] = A'[M,K3] @ B'[N,K3]^T  (bf16x3 split operands, fp32 accum)
// EPI: 0 = +bias -> fp32 C ; 1 = +bias+res -> fp32 C ; 2 = gelu(+bias) -> split bf16 Cs
// Block tile 128x128, BK=32, 8 warps (4 m x 2 n), warp tile 32x64.
// Smem rows padded to 40 bf16 (80B) -> ldmatrix conflict-free.
#define SROW 40

template<int EPI>
__global__ __launch_bounds__(256) void mma_gemm(
    const __nv_bfloat16* __restrict__ A, const __nv_bfloat16* __restrict__ Bw,
    const float* __restrict__ bias, const float* __restrict__ res,
    float* __restrict__ C, __nv_bfloat16* __restrict__ Cs,
    int N, int K3)
{
    __shared__ __nv_bfloat16 As[2][128 * SROW];
    __shared__ __nv_bfloat16 Bs[2][128 * SROW];

    const int tid = threadIdx.x;
    const int wid = tid >> 5, lid = tid & 31;
    const int warp_m = wid & 3;        // 0..3 -> 32 rows each
    const int warp_n = wid >> 2;       // 0..1 -> 64 cols each
    const int m0 = blockIdx.y * 128;
    const int n0 = blockIdx.x * 128;

    const uint32_t sA0 = smem_u32(As[0]), sA1 = smem_u32(As[1]);
    const uint32_t sB0 = smem_u32(Bs[0]), sB1 = smem_u32(Bs[1]);

    float acc[2][8][4];
    #pragma unroll
    for (int mt = 0; mt < 2; mt++)
        #pragma unroll
        for (int nt = 0; nt < 8; nt++)
            #pragma unroll
            for (int q = 0; q < 4; q++) acc[mt][nt][q] = 0.f;

    const int nK = K3 / 32;

    // per-thread load coords (512 16B-chunks per tile, 2 per thread)
    const int r0c = tid >> 2, c0c = (tid & 3);
    const int r1c = (tid + 256) >> 2, c1c = ((tid + 256) & 3);
    const uint32_t so0 = (uint32_t)(r0c * SROW + c0c * 8) * 2;
    const uint32_t so1 = (uint32_t)(r1c * SROW + c1c * 8) * 2;

    #define ISSUE(kt, b) do {                                                   \
        const __nv_bfloat16* Ag = A + (size_t)m0 * K3 + (size_t)(kt) * 32;      \
        const __nv_bfloat16* Bg = Bw + (size_t)n0 * K3 + (size_t)(kt) * 32;     \
        uint32_t _a = (b) ? sA1 : sA0, _b = (b) ? sB1 : sB0;                    \
        cpasync16(_a + so0, Ag + (size_t)r0c * K3 + c0c * 8);                   \
        cpasync16(_a + so1, Ag + (size_t)r1c * K3 + c1c * 8);                   \
        cpasync16(_b + so0, Bg + (size_t)r0c * K3 + c0c * 8);                   \
        cpasync16(_b + so1, Bg + (size_t)r1c * K3 + c1c * 8);                   \
        cp_commit();                                                            \
    } while (0)

    ISSUE(0, 0);

    for (int kt = 0; kt < nK; kt++) {
        const int b = kt & 1;
        if (kt + 1 < nK) {
            ISSUE(kt + 1, b ^ 1);
            asm volatile("cp.async.wait_group 1;" ::: "memory");
        } else {
            asm volatile("cp.async.wait_group 0;" ::: "memory");
        }
        __syncthreads();

        const uint32_t sAb = b ? sA1 : sA0;
        const uint32_t sBb = b ? sB1 : sB0;

        #pragma unroll
        for (int ks = 0; ks < 2; ks++) {
            const int kof = ks * 16;
            uint32_t afr[2][4];
            #pragma unroll
            for (int mt = 0; mt < 2; mt++) {
                uint32_t addr = sAb +
                    (uint32_t)((warp_m * 32 + mt * 16 + (lid & 15)) * SROW
                               + kof + (lid >> 4) * 8) * 2;
                ldm_x4(afr[mt], addr);
            }
            uint32_t bfr[4][4];
            #pragma unroll
            for (int q = 0; q < 4; q++) {
                const int grp = lid >> 3;
                const int n = warp_n * 64 + q * 16 + (grp >> 1) * 8 + (lid & 7);
                uint32_t addr = sBb +
                    (uint32_t)(n * SROW + kof + (grp & 1) * 8) * 2;
                ldm_x4(bfr[q], addr);
            }
            #pragma unroll
            for (int mt = 0; mt < 2; mt++)
                #pragma unroll
                for (int nt = 0; nt < 8; nt++)
                    mma_bf16(acc[mt][nt], afr[mt],
                             bfr[nt >> 1][(nt & 1) * 2],
                             bfr[nt >> 1][(nt & 1) * 2 + 1]);
        }
        __syncthreads();
    }
    #undef ISSUE

    // ---- epilogue (direct from fragments) ----
    const int g = lid >> 2, tig = lid & 3;
    const int row_base = m0 + warp_m * 32;
    const int col_base = n0 + warp_n * 64;
    #pragma unroll
    for (int mt = 0; mt < 2; mt++) {
        #pragma unroll
        for (int half = 0; half < 2; half++) {
            const int r = row_base + mt * 16 + g + half * 8;
            #pragma unroll
            for (int nt = 0; nt < 8; nt++) {
                const int cidx = col_base + nt * 8 + tig * 2;
                float v0 = acc[mt][nt][half * 2 + 0] + bias[cidx];
                float v1 = acc[mt][nt][half * 2 + 1] + bias[cidx + 1];
                if (EPI == 1) {
                    const float2 rv = *(const float2*)(res + (size_t)r * N + cidx);
                    v0 += rv.x; v1 += rv.y;
                }
                if (EPI == 2) {
                    v0 = 0.5f * v0 * (1.0f + erff(v0 * 0.70710678118654752f));
                    v1 = 0.5f * v1 * (1.0f + erff(v1 * 0.70710678118654752f));
                    __nv_bfloat16 h0 = __float2bfloat16(v0);
                    __nv_bfloat16 h1 = __float2bfloat16(v1);
                    __nv_bfloat16 l0 = __float2bfloat16(v0 - __bfloat162float(h0));
                    __nv_bfloat16 l1 = __float2bfloat16(v1 - __bfloat162float(h1));
                    size_t base = (size_t)r * (3 * N) + cidx;
                    *(uint32_t*)(Cs + base)         = pk2(h0, h1);
                    *(uint32_t*)(Cs + base + N)     = pk2(l0, l1);
                    *(uint32_t*)(Cs + base + 2 * N) = pk2(h0, h1);
                } else {
                    *(float2*)(C + (size_t)r * N + cidx) = make_float2(v0, v1);
                }
            }
        }
    }
}

// ================= split / prep kernels =================
// activation split: x[M,512] fp32 -> xs[M,1536] bf16 as [hi | lo | hi]
__global__ __launch_bounds__(256) void split_act(
    const float* __restrict__ x, __nv_bfloat16* __restrict__ xs)
{
    int idx = blockIdx.x * 256 + threadIdx.x;      // grid covers MM*EE exactly
    int m = idx >> 9, k = idx & 511;
    float v = x[idx];
    __nv_bfloat16 h = __float2bfloat16(v);
    __nv_bfloat16 l = __float2bfloat16(v - __bfloat162float(h));
    size_t base = (size_t)m * K3E;
    xs[base + k] = h; xs[base + EE + k] = l; xs[base + 2*EE + k] = h;
}

// weight split+transpose: W[K,N] fp32 -> Ws[N,3K] bf16 as [hi | hi | lo]
__global__ void split_wt(const float* __restrict__ W,
                         __nv_bfloat16* __restrict__ Ws, int K, int N)
{
    __shared__ float t[32][33];
    int n0 = blockIdx.x * 32, k0 = blockIdx.y * 32;
    for (int i = threadIdx.y; i < 32; i += 8)
        t[i][threadIdx.x] = W[(size_t)(k0 + i) * N + n0 + threadIdx.x];
    __syncthreads();
    for (int i = threadIdx.y; i < 32; i += 8) {
        int n = n0 + i, k = k0 + threadIdx.x;
        float v = t[threadIdx.x][i];
        __nv_bfloat16 h = __float2bfloat16(v);
        __nv_bfloat16 l = __float2bfloat16(v - __bfloat162float(h));
        size_t base = (size_t)n * 3 * K + k;
        Ws[base] = h; Ws[base + K] = h; Ws[base + 2*K] = l;
    }
}

// ---------------- flash attention (fp32, online softmax) ----------------
// Identical to the passing R1 kernel except the epilogue writes the
// bf16x3-split ctx directly (hi|lo|hi at row stride 1536).
__global__ __launch_bounds__(256) void attn_kernel(
    const float* __restrict__ Q, const float* __restrict__ K,
    const float* __restrict__ V, __nv_bfloat16* __restrict__ Os)
{
    extern __shared__ float sm[];
    float* Qs = sm;               // [64][64], stride 64 (Q pre-scaled by 1/8)
    float* Kt = sm + 4096;        // [64 d][68] K transposed; reused as P [64 q][68]
    float* Vs = sm + 4096 + 4352; // [64 k][68]

    const int tid = threadIdx.x;
    const int tr = tid >> 4;
    const int tc = tid & 15;
    const int b = blockIdx.z, h = blockIdx.y;
    const int q0 = blockIdx.x * 64;
    const float scale = 0.125f;

    const size_t baseQ = ((size_t)(b * SS + q0)) * EE + h * DD;

    #pragma unroll
    for (int i = 0; i < 4; i++) {
        int lin = tid + i * 256;
        int row = lin >> 4;
        int c4  = (lin & 15) * 4;
        float4 v = *(const float4*)(Q + baseQ + (size_t)row * EE + c4);
        v.x *= scale; v.y *= scale; v.z *= scale; v.w *= scale;
        *(float4*)(Qs + row * 64 + c4) = v;
    }

    float m_run[4], l_run[4], acc[4][4];
    #pragma unroll
    for (int i = 0; i < 4; i++) {
        m_run[i] = -1e30f; l_run[i] = 0.f;
        #pragma unroll
        for (int j = 0; j < 4; j++) acc[i][j] = 0.f;
    }

    for (int kt = 0; kt < SS / 64; kt++) {
        const size_t baseK = ((size_t)(b * SS + kt * 64)) * EE + h * DD;
        __syncthreads();

        #pragma unroll
        for (int i = 0; i < 4; i++) {
            int lin = tid + i * 256;
            int row = lin >> 4;
            int c4  = (lin & 15) * 4;
            float4 kv = *(const float4*)(K + baseK + (size_t)row * EE + c4);
            Kt[(c4+0)*68 + row] = kv.x;
            Kt[(c4+1)*68 + row] = kv.y;
            Kt[(c4+2)*68 + row] = kv.z;
            Kt[(c4+3)*68 + row] = kv.w;
            float4 vv = *(const float4*)(V + baseK + (size_t)row * EE + c4);
            *(float4*)(Vs + row * 68 + c4) = vv;
        }
        __syncthreads();

        float s[4][4];
        #pragma unroll
        for (int i = 0; i < 4; i++)
            #pragma unroll
            for (int j = 0; j < 4; j++) s[i][j] = 0.f;

        #pragma unroll 16
        for (int d = 0; d < 64; d++) {
            float4 k4 = *(const float4*)(Kt + d * 68 + tc * 4);
            #pragma unroll
            for (int ii = 0; ii < 4; ii++) {
                float q = Qs[(tr*4 + ii) * 64 + d];
                s[ii][0] += q * k4.x;
                s[ii][1] += q * k4.y;
                s[ii][2] += q * k4.z;
                s[ii][3] += q * k4.w;
            }
        }

        #pragma unroll
        for (int ii = 0; ii < 4; ii++) {
            float mloc = fmaxf(fmaxf(s[ii][0], s[ii][1]), fmaxf(s[ii][2], s[ii][3]));
            #pragma unroll
            for (int off = 1; off < 16; off <<= 1)
                mloc = fmaxf(mloc, __shfl_xor_sync(0xffffffffu, mloc, off));
            float m_new = fmaxf(m_run[ii], mloc);
            float corr = __expf(m_run[ii] - m_new);
            m_run[ii] = m_new;
            #pragma unroll
            for (int jj = 0; jj < 4; jj++) s[ii][jj] = __expf(s[ii][jj] - m_new);
            float ls = s[ii][0] + s[ii][1] + s[ii][2] + s[ii][3];
            #pragma unroll
            for (int off = 1; off < 16; off <<= 1)
                ls += __shfl_xor_sync(0xffffffffu, ls, off);
            l_run[ii] = l_run[ii] * corr + ls;
            #pragma unroll
            for (int jj = 0; jj < 4; jj++) acc[ii][jj] *= corr;
        }

        __syncthreads();
        #pragma unroll
        for (int ii = 0; ii < 4; ii++)
            *(float4*)(Kt + (tr*4 + ii) * 68 + tc * 4) =
                make_float4(s[ii][0], s[ii][1], s[ii][2], s[ii][3]);
        __syncthreads();

        #pragma unroll 16
        for (int k = 0; k < 64; k++) {
            float4 v4 = *(const float4*)(Vs + k * 68 + tc * 4);
            #pragma unroll
            for (int ii = 0; ii < 4; ii++) {
                float p = Kt[(tr*4 + ii) * 68 + k];
                acc[ii][0] += p * v4.x;
                acc[ii][1] += p * v4.y;
                acc[ii][2] += p * v4.z;
                acc[ii][3] += p * v4.w;
            }
        }
    }

    // write split ctx (hi | lo | hi at row stride 1536)
    const size_t rowBase = (size_t)(b * SS + q0);
    #pragma unroll
    for (int ii = 0; ii < 4; ii++) {
        float inv = 1.0f / l_run[ii];
        float o0 = acc[ii][0]*inv, o1 = acc[ii][1]*inv,
              o2 = acc[ii][2]*inv, o3 = acc[ii][3]*inv;
        __nv_bfloat16 h0 = __float2bfloat16(o0), h1 = __float2bfloat16(o1),
                      h2 = __float2bfloat16(o2), h3 = __float2bfloat16(o3);
        __nv_bfloat16 l0 = __float2bfloat16(o0 - __bfloat162float(h0));
        __nv_bfloat16 l1 = __float2bfloat16(o1 - __bfloat162float(h1));
        __nv_bfloat16 l2 = __float2bfloat16(o2 - __bfloat162float(h2));
        __nv_bfloat16 l3 = __float2bfloat16(o3 - __bfloat162float(h3));
        size_t base = (rowBase + tr*4 + ii) * K3E + h * DD + tc * 4;
        *(uint2*)(Os + base)        = make_uint2(pk2(h0,h1), pk2(h2,h3));
        *(uint2*)(Os + base + EE)   = make_uint2(pk2(l0,l1), pk2(l2,l3));
        *(uint2*)(Os + base + 2*EE) = make_uint2(pk2(h0,h1), pk2(h2,h3));
    }
}

// ---------------- layernorm (optional split bf16 out) ----------------
__global__ __launch_bounds__(256) void ln_kernel(
    const float* __restrict__ x, const float* __restrict__ g,
    const float* __restrict__ be, float* __restrict__ y,
    __nv_bfloat16* __restrict__ ys)
{
    __shared__ float red[16];
    const int row = blockIdx.x;
    const int tid = threadIdx.x;
    const float* xr = x + (size_t)row * EE;

    float v0 = xr[tid], v1 = xr[tid + 256];
    float s  = v0 + v1;
    float ss = v0*v0 + v1*v1;
    #pragma unroll
    for (int off = 16; off > 0; off >>= 1) {
        s  += __shfl_xor_sync(0xffffffffu, s,  off);
        ss += __shfl_xor_sync(0xffffffffu, ss, off);
    }
    int wid = tid >> 5, lid = tid & 31;
    if (lid == 0) { red[wid] = s; red[wid + 8] = ss; }
    __syncthreads();
    if (tid < 32) {
        float a = (tid < 8)  ? red[tid]     : 0.f;
        float c = (tid < 8)  ? red[tid + 8] : 0.f;
        #pragma unroll
        for (int off = 4; off > 0; off >>= 1) {
            a += __shfl_xor_sync(0xffffffffu, a, off);
            c += __shfl_xor_sync(0xffffffffu, c, off);
        }
        if (tid == 0) { red[0] = a; red[1] = c; }
    }
    __syncthreads();
    float mean = red[0] * (1.0f / EE);
    float var  = fmaxf(red[1] * (1.0f / EE) - mean * mean, 0.f);
    float rstd = rsqrtf(var + LN_EPS);

    float o0 = (v0 - mean) * rstd * g[tid]       + be[tid];
    float o1 = (v1 - mean) * rstd * g[tid + 256] + be[tid + 256];
    float* yr = y + (size_t)row * EE;
    yr[tid] = o0; yr[tid + 256] = o1;

    if (ys) {
        size_t base = (size_t)row * K3E;
        __nv_bfloat16 h0 = __float2bfloat16(o0);
        __nv_bfloat16 h1 = __float2bfloat16(o1);
        __nv_bfloat16 q0 = __float2bfloat16(o0 - __bfloat162float(h0));
        __nv_bfloat16 q1 = __float2bfloat16(o1 - __bfloat162float(h1));
        ys[base + tid]            = h0;  ys[base + tid + 256]            = h1;
        ys[base + EE + tid]       = q0;  ys[base + EE + tid + 256]       = q1;
        ys[base + 2*EE + tid]     = h0;  ys[base + 2*EE + tid + 256]     = h1;
    }
}

// ---------------- launch ----------------
extern "C" void kernel_launch(void* const* d_in, const int* in_sizes, int n_in,
                              void* d_out, int out_size)
{
    (void)in_sizes; (void)n_in; (void)out_size;
    const float* query = (const float*)d_in[0];
    const float* key_t = (const float*)d_in[1];
    const float* value = (const float*)d_in[2];
    const float* Wq = (const float*)d_in[3];  const float* bq = (const float*)d_in[4];
    const float* Wk = (const float*)d_in[5];  const float* bk = (const float*)d_in[6];
    const float* Wv = (const float*)d_in[7];  const float* bv = (const float*)d_in[8];
    const float* Wo = (const float*)d_in[9];  const float* bo = (const float*)d_in[10];
    const float* g1 = (const float*)d_in[11]; const float* be1 = (const float*)d_in[12];
    const float* g2 = (const float*)d_in[13]; const float* be2 = (const float*)d_in[14];
    const float* W1 = (const float*)d_in[15]; const float* b1 = (const float*)d_in[16];
    const float* W2 = (const float*)d_in[17]; const float* b2 = (const float*)d_in[18];
    float* out = (float*)d_out;

    void *pQ, *pK, *pV, *pTmp, *pX1, *pA, *pB, *pW;
    cudaGetSymbolAddress(&pQ,   g_Q);
    cudaGetSymbolAddress(&pK,   g_K);
    cudaGetSymbolAddress(&pV,   g_V);
    cudaGetSymbolAddress(&pTmp, g_tmp);
    cudaGetSymbolAddress(&pX1,  g_x1);
    cudaGetSymbolAddress(&pA,   g_actA);
    cudaGetSymbolAddress(&pB,   g_actB);
    cudaGetSymbolAddress(&pW,   g_ws);
    float* fQ = (float*)pQ;   float* fK = (float*)pK;  float* fV = (float*)pV;
    float* fT = (float*)pTmp; float* fX = (float*)pX1;
    __nv_bfloat16* actA = (__nv_bfloat16*)pA;
    __nv_bfloat16* actB = (__nv_bfloat16*)pB;
    __nv_bfloat16* ws   = (__nv_bfloat16*)pW;

    const int ATTN_SMEM = (4096 + 4352 + 4352) * 4;  // 51200 bytes
    cudaFuncSetAttribute(attn_kernel,
                         cudaFuncAttributeMaxDynamicSharedMemorySize, ATTN_SMEM);

    dim3 gE(EE / 128, MM / 128);          // (4, 64)
    dim3 gF(FF / 128, MM / 128);          // (16, 64)
    dim3 wEE(EE / 32, EE / 32), wEF(FF / 32, EE / 32), wFE(EE / 32, FF / 32);
    dim3 wblk(32, 8);
    int splitBlocks = MM * EE / 256;

    // Q projection
    split_act<<<splitBlocks, 256>>>(query, actA);
    split_wt<<<wEE, wblk>>>(Wq, ws, EE, EE);
    mma_gemm<0><<<gE, 256>>>(actA, ws, bq, nullptr, fQ, nullptr, EE, K3E);
    // K projection
    split_act<<<splitBlocks, 256>>>(key_t, actA);
    split_wt<<<wEE, wblk>>>(Wk, ws, EE, EE);
    mma_gemm<0><<<gE, 256>>>(actA, ws, bk, nullptr, fK, nullptr, EE, K3E);
    // V projection
    split_act<<<splitBlocks, 256>>>(value, actA);
    split_wt<<<wEE, wblk>>>(Wv, ws, EE, EE);
    mma_gemm<0><<<gE, 256>>>(actA, ws, bv, nullptr, fV, nullptr, EE, K3E);

    // flash attention -> split ctx in actA
    attn_kernel<<<dim3(SS / 64, HH, BB), 256, ATTN_SMEM>>>(fQ, fK, fV, actA);

    // O projection + residual(query)
    split_wt<<<wEE, wblk>>>(Wo, ws, EE, EE);
    mma_gemm<1><<<gE, 256>>>(actA, ws, bo, query, fT, nullptr, EE, K3E);
    // LN1 -> x1 fp32 + split in actA
    ln_kernel<<<MM, 256>>>(fT, g1, be1, fX, actA);
    // FFN1 + exact GELU -> split output in actB
    split_wt<<<wEF, wblk>>>(W1, ws, EE, FF);
    mma_gemm<2><<<gF, 256>>>(actA, ws, b1, nullptr, nullptr, actB, FF, K3E);
    // FFN2 + residual(x1)
    split_wt<<<wFE, wblk>>>(W2, ws, FF, EE);
    mma_gemm<1><<<gE, 256>>>(actB, ws, b2, fX, fT, nullptr, EE, K3F);
    // LN2 -> out
    ln_kernel<<<MM, 256>>>(fT, g2, be2, out, nullptr);
}

// round 7
// speedup vs baseline: 2.7103x; 1.9991x over previous
#include <cuda_runtime.h>
#include <cuda_bf16.h>
#include <math.h>
#include <stdint.h>

// Problem dims (fixed)
#define BB 4
#define SS 2048
#define EE 512
#define HH 8
#define DD 64
#define FF 2048
#define MM (BB*SS)          // 8192 tokens
#define LN_EPS 1e-5f
#define K3E (3*EE)          // 1536
#define K3F (3*FF)          // 6144

// ---------------- scratch (device globals; no allocation) ----------------
__device__ __nv_bfloat16 g_Qb[(size_t)MM*EE];
__device__ __nv_bfloat16 g_Kb[(size_t)MM*EE];
__device__ __nv_bfloat16 g_Vb[(size_t)MM*EE];
__device__ float g_tmp[MM*EE];
__device__ float g_x1 [MM*EE];
__device__ __nv_bfloat16 g_actA[(size_t)MM*K3E];   // split activations (K=512 stages)
__device__ __nv_bfloat16 g_actB[(size_t)MM*K3F];   // split FFN1 output (K=2048 stage)
__device__ __nv_bfloat16 g_ws  [(size_t)FF*K3E];   // split weights

// ================= helpers =================
__device__ __forceinline__ uint32_t smem_u32(const void* p) {
    uint32_t a;
    asm("{ .reg .u64 t; cvta.to.shared.u64 t, %1; cvt.u32.u64 %0, t; }"
        : "=r"(a) : "l"(p));
    return a;
}
__device__ __forceinline__ void cpasync16(uint32_t s, const void* g) {
    asm volatile("cp.async.cg.shared.global [%0], [%1], 16;" :: "r"(s), "l"(g));
}
__device__ __forceinline__ void cp_commit() {
    asm volatile("cp.async.commit_group;" ::: "memory");
}
__device__ __forceinline__ void ldm_x4(uint32_t* r, uint32_t addr) {
    asm volatile("ldmatrix.sync.aligned.m8n8.x4.shared.b16 {%0,%1,%2,%3}, [%4];"
        : "=r"(r[0]), "=r"(r[1]), "=r"(r[2]), "=r"(r[3]) : "r"(addr));
}
__device__ __forceinline__ void ldm_x4_t(uint32_t* r, uint32_t addr) {
    asm volatile("ldmatrix.sync.aligned.m8n8.x4.trans.shared.b16 {%0,%1,%2,%3}, [%4];"
        : "=r"(r[0]), "=r"(r[1]), "=r"(r[2]), "=r"(r[3]) : "r"(addr));
}
__device__ __forceinline__ void mma_bf16(float* c, const uint32_t* a,
                                         uint32_t b0, uint32_t b1) {
    asm volatile(
        "mma.sync.aligned.m16n8k16.row.col.f32.bf16.bf16.f32 "
        "{%0,%1,%2,%3}, {%4,%5,%6,%7}, {%8,%9}, {%0,%1,%2,%3};"
        : "+f"(c[0]), "+f"(c[1]), "+f"(c[2]), "+f"(c[3])
        : "r"(a[0]), "r"(a[1]), "r"(a[2]), "r"(a[3]), "r"(b0), "r"(b1));
}
__device__ __forceinline__ uint32_t pk2(__nv_bfloat16 a, __nv_bfloat16 b) {
    __nv_bfloat162 t = __halves2bfloat162(a, b);
    return *reinterpret_cast<uint32_t*>(&t);
}
__device__ __forceinline__ uint32_t pk2f(float a, float b) {
    return pk2(__float2bfloat16(a), __float2bfloat16(b));
}

// ================= HMMA (mma.sync) GEMM =================
// C[M,N] = A'[M,K3] @ B'[N,K3]^T  (bf16x3 split operands, fp32 accum)
// EPI: 0 = +bias fp32 ; 1 = +bias+res fp32 ; 2 = gelu(+bias) -> split bf16 ;
//      3 = +bias -> plain bf16
#define SROW 40

template<int EPI>
__global__ __launch_bounds__(256) void mma_gemm(
    const __nv_bfloat16* __restrict__ A, const __nv_bfloat16* __restrict__ Bw,
    const float* __restrict__ bias, const float* __restrict__ res,
    float* __restrict__ C, __nv_bfloat16* __restrict__ Cs,
    int N, int K3)
{
    __shared__ __nv_bfloat16 As[2][128 * SROW];
    __shared__ __nv_bfloat16 Bs[2][128 * SROW];

    const int tid = threadIdx.x;
    const int wid = tid >> 5, lid = tid & 31;
    const int warp_m = wid & 3;
    const int warp_n = wid >> 2;
    const int m0 = blockIdx.y * 128;
    const int n0 = blockIdx.x * 128;

    const uint32_t sA0 = smem_u32(As[0]), sA1 = smem_u32(As[1]);
    const uint32_t sB0 = smem_u32(Bs[0]), sB1 = smem_u32(Bs[1]);

    float acc[2][8][4];
    #pragma unroll
    for (int mt = 0; mt < 2; mt++)
        #pragma unroll
        for (int nt = 0; nt < 8; nt++)
            #pragma unroll
            for (int q = 0; q < 4; q++) acc[mt][nt][q] = 0.f;

    const int nK = K3 / 32;

    const int r0c = tid >> 2, c0c = (tid & 3);
    const int r1c = (tid + 256) >> 2, c1c = ((tid + 256) & 3);
    const uint32_t so0 = (uint32_t)(r0c * SROW + c0c * 8) * 2;
    const uint32_t so1 = (uint32_t)(r1c * SROW + c1c * 8) * 2;

    #define ISSUE(kt, b) do {                                                   \
        const __nv_bfloat16* Ag = A + (size_t)m0 * K3 + (size_t)(kt) * 32;      \
        const __nv_bfloat16* Bg = Bw + (size_t)n0 * K3 + (size_t)(kt) * 32;     \
        uint32_t _a = (b) ? sA1 : sA0, _b = (b) ? sB1 : sB0;                    \
        cpasync16(_a + so0, Ag + (size_t)r0c * K3 + c0c * 8);                   \
        cpasync16(_a + so1, Ag + (size_t)r1c * K3 + c1c * 8);                   \
        cpasync16(_b + so0, Bg + (size_t)r0c * K3 + c0c * 8);                   \
        cpasync16(_b + so1, Bg + (size_t)r1c * K3 + c1c * 8);                   \
        cp_commit();                                                            \
    } while (0)

    ISSUE(0, 0);

    for (int kt = 0; kt < nK; kt++) {
        const int b = kt & 1;
        if (kt + 1 < nK) {
            ISSUE(kt + 1, b ^ 1);
            asm volatile("cp.async.wait_group 1;" ::: "memory");
        } else {
            asm volatile("cp.async.wait_group 0;" ::: "memory");
        }
        __syncthreads();

        const uint32_t sAb = b ? sA1 : sA0;
        const uint32_t sBb = b ? sB1 : sB0;

        #pragma unroll
        for (int ks = 0; ks < 2; ks++) {
            const int kof = ks * 16;
            uint32_t afr[2][4];
            #pragma unroll
            for (int mt = 0; mt < 2; mt++) {
                uint32_t addr = sAb +
                    (uint32_t)((warp_m * 32 + mt * 16 + (lid & 15)) * SROW
                               + kof + (lid >> 4) * 8) * 2;
                ldm_x4(afr[mt], addr);
            }
            uint32_t bfr[4][4];
            #pragma unroll
            for (int q = 0; q < 4; q++) {
                const int grp = lid >> 3;
                const int n = warp_n * 64 + q * 16 + (grp >> 1) * 8 + (lid & 7);
                uint32_t addr = sBb +
                    (uint32_t)(n * SROW + kof + (grp & 1) * 8) * 2;
                ldm_x4(bfr[q], addr);
            }
            #pragma unroll
            for (int mt = 0; mt < 2; mt++)
                #pragma unroll
                for (int nt = 0; nt < 8; nt++)
                    mma_bf16(acc[mt][nt], afr[mt],
                             bfr[nt >> 1][(nt & 1) * 2],
                             bfr[nt >> 1][(nt & 1) * 2 + 1]);
        }
        __syncthreads();
    }
    #undef ISSUE

    // ---- epilogue (direct from fragments) ----
    const int g = lid >> 2, tig = lid & 3;
    const int row_base = m0 + warp_m * 32;
    const int col_base = n0 + warp_n * 64;
    #pragma unroll
    for (int mt = 0; mt < 2; mt++) {
        #pragma unroll
        for (int half = 0; half < 2; half++) {
            const int r = row_base + mt * 16 + g + half * 8;
            #pragma unroll
            for (int nt = 0; nt < 8; nt++) {
                const int cidx = col_base + nt * 8 + tig * 2;
                float v0 = acc[mt][nt][half * 2 + 0] + bias[cidx];
                float v1 = acc[mt][nt][half * 2 + 1] + bias[cidx + 1];
                if (EPI == 1) {
                    const float2 rv = *(const float2*)(res + (size_t)r * N + cidx);
                    v0 += rv.x; v1 += rv.y;
                }
                if (EPI == 2) {
                    v0 = 0.5f * v0 * (1.0f + erff(v0 * 0.70710678118654752f));
                    v1 = 0.5f * v1 * (1.0f + erff(v1 * 0.70710678118654752f));
                    __nv_bfloat16 h0 = __float2bfloat16(v0);
                    __nv_bfloat16 h1 = __float2bfloat16(v1);
                    __nv_bfloat16 l0 = __float2bfloat16(v0 - __bfloat162float(h0));
                    __nv_bfloat16 l1 = __float2bfloat16(v1 - __bfloat162float(h1));
                    size_t base = (size_t)r * (3 * N) + cidx;
                    *(uint32_t*)(Cs + base)         = pk2(h0, h1);
                    *(uint32_t*)(Cs + base + N)     = pk2(l0, l1);
                    *(uint32_t*)(Cs + base + 2 * N) = pk2(h0, h1);
                } else if (EPI == 3) {
                    *(uint32_t*)(Cs + (size_t)r * N + cidx) = pk2f(v0, v1);
                } else {
                    *(float2*)(C + (size_t)r * N + cidx) = make_float2(v0, v1);
                }
            }
        }
    }
}

// ================= HMMA flash attention =================
// 128 q-rows / CTA, 8 warps x 16 rows, 64-key blocks, double-buffered K/V.
// Q,K,V bf16 [M,512]; output: split hi|lo|hi bf16 ctx [M, 1536].
#define AST 72   // smem row stride (bf16 elems) = 144B -> ldmatrix conflict-free

__global__ __launch_bounds__(256, 2) void attn_mma(
    const __nv_bfloat16* __restrict__ Q, const __nv_bfloat16* __restrict__ K,
    const __nv_bfloat16* __restrict__ V, __nv_bfloat16* __restrict__ Os)
{
    extern __shared__ __nv_bfloat16 smem[];
    const uint32_t sQ = smem_u32(smem);                       // 128*72
    const uint32_t sK0 = sQ + 128 * AST * 2;                  // 64*72 each
    const uint32_t sV0 = sK0 + 64 * AST * 2;
    const uint32_t sK1 = sV0 + 64 * AST * 2;
    const uint32_t sV1 = sK1 + 64 * AST * 2;

    const int tid = threadIdx.x;
    const int wid = tid >> 5, lid = tid & 31;
    const int g = lid >> 2, tig = lid & 3;
    const int h = blockIdx.y, b = blockIdx.z;
    const int q0 = blockIdx.x * 128;

    const __nv_bfloat16* Qg = Q + ((size_t)(b * SS + q0)) * EE + h * DD;
    const __nv_bfloat16* Kg = K + ((size_t)(b * SS)) * EE + h * DD;
    const __nv_bfloat16* Vg = V + ((size_t)(b * SS)) * EE + h * DD;

    // Q tile: 128 rows x 128B = 1024 chunks
    #pragma unroll
    for (int i = 0; i < 4; i++) {
        int idx = tid + i * 256;
        int row = idx >> 3, c8 = (idx & 7) * 8;
        cpasync16(sQ + (uint32_t)(row * AST + c8) * 2, Qg + (size_t)row * EE + c8);
    }

    #define KV_ISSUE(kt, kbuf, vbuf) do {                                   \
        int base_ = (kt) * 64;                                              \
        _Pragma("unroll")                                                   \
        for (int i_ = 0; i_ < 2; i_++) {                                    \
            int idx_ = tid + i_ * 256;                                      \
            int row_ = idx_ >> 3, c8_ = (idx_ & 7) * 8;                     \
            cpasync16((kbuf) + (uint32_t)(row_ * AST + c8_) * 2,            \
                      Kg + (size_t)(base_ + row_) * EE + c8_);              \
            cpasync16((vbuf) + (uint32_t)(row_ * AST + c8_) * 2,            \
                      Vg + (size_t)(base_ + row_) * EE + c8_);              \
        }                                                                   \
        cp_commit();                                                        \
    } while (0)

    KV_ISSUE(0, sK0, sV0);   // same group as Q

    float m_run[2] = {-1e30f, -1e30f}, l_run[2] = {0.f, 0.f};
    float oacc[8][4];
    #pragma unroll
    for (int nt = 0; nt < 8; nt++)
        #pragma unroll
        for (int q = 0; q < 4; q++) oacc[nt][q] = 0.f;

    uint32_t qfr[4][4];

    for (int kt = 0; kt < SS / 64; kt++) {
        const int buf = kt & 1;
        const uint32_t kb = buf ? sK1 : sK0;
        const uint32_t vb = buf ? sV1 : sV0;
        if (kt + 1 < SS / 64) {
            const uint32_t nk = buf ? sK0 : sK1;
            const uint32_t nv = buf ? sV0 : sV1;
            KV_ISSUE(kt + 1, nk, nv);
            asm volatile("cp.async.wait_group 1;" ::: "memory");
        } else {
            asm volatile("cp.async.wait_group 0;" ::: "memory");
        }
        __syncthreads();

        if (kt == 0) {   // Qs ready after first wait
            #pragma unroll
            for (int ks = 0; ks < 4; ks++) {
                uint32_t addr = sQ +
                    (uint32_t)((wid * 16 + (lid & 15)) * AST + ks * 16 + (lid >> 4) * 8) * 2;
                ldm_x4(qfr[ks], addr);
            }
        }

        // ---- S = Q @ K^T ----
        float sfr[8][4];
        #pragma unroll
        for (int nt = 0; nt < 8; nt++)
            #pragma unroll
            for (int q = 0; q < 4; q++) sfr[nt][q] = 0.f;

        const int grp = lid >> 3;
        #pragma unroll
        for (int ks = 0; ks < 4; ks++) {
            uint32_t bfr[4][4];
            #pragma unroll
            for (int q = 0; q < 4; q++) {
                const int n = q * 16 + (grp >> 1) * 8 + (lid & 7);
                uint32_t addr = kb + (uint32_t)(n * AST + ks * 16 + (grp & 1) * 8) * 2;
                ldm_x4(bfr[q], addr);
            }
            #pragma unroll
            for (int nt = 0; nt < 8; nt++)
                mma_bf16(sfr[nt], qfr[ks],
                         bfr[nt >> 1][(nt & 1) * 2],
                         bfr[nt >> 1][(nt & 1) * 2 + 1]);
        }

        // ---- online softmax (rows g, g+8; quad lanes share a row) ----
        #pragma unroll
        for (int half = 0; half < 2; half++) {
            float mloc = -1e30f;
            #pragma unroll
            for (int nt = 0; nt < 8; nt++) {
                sfr[nt][half*2]   *= 0.125f;
                sfr[nt][half*2+1] *= 0.125f;
                mloc = fmaxf(mloc, fmaxf(sfr[nt][half*2], sfr[nt][half*2+1]));
            }
            mloc = fmaxf(mloc, __shfl_xor_sync(0xffffffffu, mloc, 1));
            mloc = fmaxf(mloc, __shfl_xor_sync(0xffffffffu, mloc, 2));
            float m_new = fmaxf(m_run[half], mloc);
            float corr = __expf(m_run[half] - m_new);
            m_run[half] = m_new;
            float lsum = 0.f;
            #pragma unroll
            for (int nt = 0; nt < 8; nt++) {
                float p0 = __expf(sfr[nt][half*2]   - m_new);
                float p1 = __expf(sfr[nt][half*2+1] - m_new);
                sfr[nt][half*2] = p0; sfr[nt][half*2+1] = p1;
                lsum += p0 + p1;
            }
            lsum += __shfl_xor_sync(0xffffffffu, lsum, 1);
            lsum += __shfl_xor_sync(0xffffffffu, lsum, 2);
            l_run[half] = l_run[half] * corr + lsum;
            #pragma unroll
            for (int nt = 0; nt < 8; nt++) {
                oacc[nt][half*2]   *= corr;
                oacc[nt][half*2+1] *= corr;
            }
        }

        // ---- O += P @ V  (P packed in regs as A-frags; V via ldmatrix.trans) ----
        #pragma unroll
        for (int j = 0; j < 4; j++) {
            uint32_t pfr[4];
            pfr[0] = pk2f(sfr[2*j][0],   sfr[2*j][1]);
            pfr[1] = pk2f(sfr[2*j][2],   sfr[2*j][3]);
            pfr[2] = pk2f(sfr[2*j+1][0], sfr[2*j+1][1]);
            pfr[3] = pk2f(sfr[2*j+1][2], sfr[2*j+1][3]);
            #pragma unroll
            for (int dp = 0; dp < 4; dp++) {
                uint32_t vfr[4];
                uint32_t addr = vb +
                    (uint32_t)((j * 16 + (lid & 15)) * AST + dp * 16 + (lid >> 4) * 8) * 2;
                ldm_x4_t(vfr, addr);
                mma_bf16(oacc[dp*2],     pfr, vfr[0], vfr[1]);
                mma_bf16(oacc[dp*2 + 1], pfr, vfr[2], vfr[3]);
            }
        }
        __syncthreads();
    }
    #undef KV_ISSUE

    // ---- epilogue: split hi|lo|hi ctx ----
    const size_t rowBase = (size_t)(b * SS + q0);
    #pragma unroll
    for (int half = 0; half < 2; half++) {
        float inv = 1.0f / l_run[half];
        size_t m = rowBase + wid * 16 + g + half * 8;
        size_t base = m * K3E + h * DD + tig * 2;
        #pragma unroll
        for (int nt = 0; nt < 8; nt++) {
            float o0 = oacc[nt][half*2]     * inv;
            float o1 = oacc[nt][half*2 + 1] * inv;
            __nv_bfloat16 h0 = __float2bfloat16(o0);
            __nv_bfloat16 h1 = __float2bfloat16(o1);
            __nv_bfloat16 l0 = __float2bfloat16(o0 - __bfloat162float(h0));
            __nv_bfloat16 l1 = __float2bfloat16(o1 - __bfloat162float(h1));
            size_t off = base + nt * 8;
            *(uint32_t*)(Os + off)          = pk2(h0, h1);
            *(uint32_t*)(Os + off + EE)     = pk2(l0, l1);
            *(uint32_t*)(Os + off + 2*EE)   = pk2(h0, h1);
        }
    }
}

// ================= split / prep kernels =================
__global__ __launch_bounds__(256) void split_act(
    const float* __restrict__ x, __nv_bfloat16* __restrict__ xs)
{
    int idx = blockIdx.x * 256 + threadIdx.x;
    int m = idx >> 9, k = idx & 511;
    float v = x[idx];
    __nv_bfloat16 h = __float2bfloat16(v);
    __nv_bfloat16 l = __float2bfloat16(v - __bfloat162float(h));
    size_t base = (size_t)m * K3E;
    xs[base + k] = h; xs[base + EE + k] = l; xs[base + 2*EE + k] = h;
}

__global__ void split_wt(const float* __restrict__ W,
                         __nv_bfloat16* __restrict__ Ws, int K, int N)
{
    __shared__ float t[32][33];
    int n0 = blockIdx.x * 32, k0 = blockIdx.y * 32;
    for (int i = threadIdx.y; i < 32; i += 8)
        t[i][threadIdx.x] = W[(size_t)(k0 + i) * N + n0 + threadIdx.x];
    __syncthreads();
    for (int i = threadIdx.y; i < 32; i += 8) {
        int n = n0 + i, k = k0 + threadIdx.x;
        float v = t[threadIdx.x][i];
        __nv_bfloat16 h = __float2bfloat16(v);
        __nv_bfloat16 l = __float2bfloat16(v - __bfloat162float(h));
        size_t base = (size_t)n * 3 * K + k;
        Ws[base] = h; Ws[base + K] = h; Ws[base + 2*K] = l;
    }
}

// ---------------- layernorm (optional split bf16 out) ----------------
__global__ __launch_bounds__(256) void ln_kernel(
    const float* __restrict__ x, const float* __restrict__ g,
    const float* __restrict__ be, float* __restrict__ y,
    __nv_bfloat16* __restrict__ ys)
{
    __shared__ float red[16];
    const int row = blockIdx.x;
    const int tid = threadIdx.x;
    const float* xr = x + (size_t)row * EE;

    float v0 = xr[tid], v1 = xr[tid + 256];
    float s  = v0 + v1;
    float ss = v0*v0 + v1*v1;
    #pragma unroll
    for (int off = 16; off > 0; off >>= 1) {
        s  += __shfl_xor_sync(0xffffffffu, s,  off);
        ss += __shfl_xor_sync(0xffffffffu, ss, off);
    }
    int wid = tid >> 5, lid = tid & 31;
    if (lid == 0) { red[wid] = s; red[wid + 8] = ss; }
    __syncthreads();
    if (tid < 32) {
        float a = (tid < 8)  ? red[tid]     : 0.f;
        float c = (tid < 8)  ? red[tid + 8] : 0.f;
        #pragma unroll
        for (int off = 4; off > 0; off >>= 1) {
            a += __shfl_xor_sync(0xffffffffu, a, off);
            c += __shfl_xor_sync(0xffffffffu, c, off);
        }
        if (tid == 0) { red[0] = a; red[1] = c; }
    }
    __syncthreads();
    float mean = red[0] * (1.0f / EE);
    float var  = fmaxf(red[1] * (1.0f / EE) - mean * mean, 0.f);
    float rstd = rsqrtf(var + LN_EPS);

    float o0 = (v0 - mean) * rstd * g[tid]       + be[tid];
    float o1 = (v1 - mean) * rstd * g[tid + 256] + be[tid + 256];
    float* yr = y + (size_t)row * EE;
    yr[tid] = o0; yr[tid + 256] = o1;

    if (ys) {
        size_t base = (size_t)row * K3E;
        __nv_bfloat16 h0 = __float2bfloat16(o0);
        __nv_bfloat16 h1 = __float2bfloat16(o1);
        __nv_bfloat16 q0 = __float2bfloat16(o0 - __bfloat162float(h0));
        __nv_bfloat16 q1 = __float2bfloat16(o1 - __bfloat162float(h1));
        ys[base + tid]            = h0;  ys[base + tid + 256]            = h1;
        ys[base + EE + tid]       = q0;  ys[base + EE + tid + 256]       = q1;
        ys[base + 2*EE + tid]     = h0;  ys[base + 2*EE + tid + 256]     = h1;
    }
}

// ---------------- launch ----------------
extern "C" void kernel_launch(void* const* d_in, const int* in_sizes, int n_in,
                              void* d_out, int out_size)
{
    (void)in_sizes; (void)n_in; (void)out_size;
    const float* query = (const float*)d_in[0];
    const float* key_t = (const float*)d_in[1];
    const float* value = (const float*)d_in[2];
    const float* Wq = (const float*)d_in[3];  const float* bq = (const float*)d_in[4];
    const float* Wk = (const float*)d_in[5];  const float* bk = (const float*)d_in[6];
    const float* Wv = (const float*)d_in[7];  const float* bv = (const float*)d_in[8];
    const float* Wo = (const float*)d_in[9];  const float* bo = (const float*)d_in[10];
    const float* g1 = (const float*)d_in[11]; const float* be1 = (const float*)d_in[12];
    const float* g2 = (const float*)d_in[13]; const float* be2 = (const float*)d_in[14];
    const float* W1 = (const float*)d_in[15]; const float* b1 = (const float*)d_in[16];
    const float* W2 = (const float*)d_in[17]; const float* b2 = (const float*)d_in[18];
    float* out = (float*)d_out;

    void *pQ, *pK, *pV, *pTmp, *pX1, *pA, *pB, *pW;
    cudaGetSymbolAddress(&pQ,   g_Qb);
    cudaGetSymbolAddress(&pK,   g_Kb);
    cudaGetSymbolAddress(&pV,   g_Vb);
    cudaGetSymbolAddress(&pTmp, g_tmp);
    cudaGetSymbolAddress(&pX1,  g_x1);
    cudaGetSymbolAddress(&pA,   g_actA);
    cudaGetSymbolAddress(&pB,   g_actB);
    cudaGetSymbolAddress(&pW,   g_ws);
    __nv_bfloat16* bQ = (__nv_bfloat16*)pQ;
    __nv_bfloat16* bK = (__nv_bfloat16*)pK;
    __nv_bfloat16* bV = (__nv_bfloat16*)pV;
    float* fT = (float*)pTmp; float* fX = (float*)pX1;
    __nv_bfloat16* actA = (__nv_bfloat16*)pA;
    __nv_bfloat16* actB = (__nv_bfloat16*)pB;
    __nv_bfloat16* ws   = (__nv_bfloat16*)pW;

    const int ATTN_SMEM = (128 * AST + 4 * 64 * AST) * 2;  // 55296 bytes
    cudaFuncSetAttribute(attn_mma,
                         cudaFuncAttributeMaxDynamicSharedMemorySize, ATTN_SMEM);

    dim3 gE(EE / 128, MM / 128);          // (4, 64)
    dim3 gF(FF / 128, MM / 128);          // (16, 64)
    dim3 wEE(EE / 32, EE / 32), wEF(FF / 32, EE / 32), wFE(EE / 32, FF / 32);
    dim3 wblk(32, 8);
    int splitBlocks = MM * EE / 256;

    // QKV projections -> bf16 outputs
    split_act<<<splitBlocks, 256>>>(query, actA);
    split_wt<<<wEE, wblk>>>(Wq, ws, EE, EE);
    mma_gemm<3><<<gE, 256>>>(actA, ws, bq, nullptr, nullptr, bQ, EE, K3E);
    split_act<<<splitBlocks, 256>>>(key_t, actA);
    split_wt<<<wEE, wblk>>>(Wk, ws, EE, EE);
    mma_gemm<3><<<gE, 256>>>(actA, ws, bk, nullptr, nullptr, bK, EE, K3E);
    split_act<<<splitBlocks, 256>>>(value, actA);
    split_wt<<<wEE, wblk>>>(Wv, ws, EE, EE);
    mma_gemm<3><<<gE, 256>>>(actA, ws, bv, nullptr, nullptr, bV, EE, K3E);

    // HMMA flash attention -> split ctx in actA
    attn_mma<<<dim3(SS / 128, HH, BB), 256, ATTN_SMEM>>>(bQ, bK, bV, actA);

    // O projection + residual(query)
    split_wt<<<wEE, wblk>>>(Wo, ws, EE, EE);
    mma_gemm<1><<<gE, 256>>>(actA, ws, bo, query, fT, nullptr, EE, K3E);
    // LN1 -> x1 fp32 + split in actA
    ln_kernel<<<MM, 256>>>(fT, g1, be1, fX, actA);
    // FFN1 + exact GELU -> split output in actB
    split_wt<<<wEF, wblk>>>(W1, ws, EE, FF);
    mma_gemm<2><<<gF, 256>>>(actA, ws, b1, nullptr, nullptr, actB, FF, K3E);
    // FFN2 + residual(x1)
    split_wt<<<wFE, wblk>>>(W2, ws, FF, EE);
    mma_gemm<1><<<gE, 256>>>(actB, ws, b2, fX, fT, nullptr, EE, K3F);
    // LN2 -> out
    ln_kernel<<<MM, 256>>>(fT, g2, be2, out, nullptr);
}